// round 14
// baseline (speedup 1.0000x reference)
#include <cuda_runtime.h>
#include <cuda_pipeline.h>
#include <math.h>
#include <mma.h>
using namespace nvcuda;

#define Bz   64
#define Lz   25
#define Fz   128
#define Pz   10000
#define Cz   400
#define BL   1600
#define SLC  (Lz * Fz)          // 3200
#define WPAD 132
#define WHS  (64 * WPAD)        // 8448 floats
#define PTILES 79               // ceil(10000/128)
#define PES  136                // padded pe row stride (floats)

// ---------------- device scratch -------------------------------------------------
__device__ __align__(16) float g_st[10][BL * Fz];
__device__ __align__(16) float g_v8[8][BL * Fz];
__device__ __align__(16) float g_meanH[8][2 * Bz * Lz];
__device__ __align__(16) float g_pe[10240 * Fz];
__device__ unsigned g_maxbits = 0u;
__device__ unsigned g_minbits = 0x7F7FFFFFu;

// ================= embed ==========================================================
__global__ void __launch_bounds__(256) k_embed(
        const int* __restrict__ user, const int* __restrict__ poi,
        const int* __restrict__ cat,  const int* __restrict__ tod,
        const int* __restrict__ dow,
        const float* __restrict__ ue,  const float* __restrict__ pe,
        const float* __restrict__ ce,  const float* __restrict__ te,
        const float* __restrict__ de,  const float* __restrict__ uec,
        const float* __restrict__ tec, const float* __restrict__ dec) {
    int r = 2 * blockIdx.x + (threadIdx.x >> 7);
    int d = threadIdx.x & 127;
    int u = user[r], p = poi[r], c = cat[r], td = tod[r], dw = dow[r];
    g_st[0][r * Fz + d] = ue[u * Fz + d]  + pe[p * Fz + d] + te[td * Fz + d]  + de[dw * Fz + d];
    g_st[1][r * Fz + d] = uec[u * Fz + d] + ce[c * Fz + d] + tec[td * Fz + d] + dec[dw * Fz + d];
}

// ================= side stream: minmax over gathered D rows ======================
__global__ void __launch_bounds__(256) k_minmax(const int* __restrict__ poi,
                                                const float* __restrict__ Dm) {
    __shared__ float smx[256], smn[256];
    const int t = threadIdx.x;
    int rid = blockIdx.x;
    int row = poi[rid >> 1];
    int part = rid & 1;
    const float4* rp4 = (const float4*)(Dm + (size_t)row * Pz);
    float mx = -1e30f, mn = 1e30f;
    for (int p = part * 1250 + t; p < (part + 1) * 1250; p += 256) {
        float4 v = __ldg(rp4 + p);
        mx = fmaxf(mx, fmaxf(fmaxf(v.x, v.y), fmaxf(v.z, v.w)));
        mn = fminf(mn, fminf(fminf(v.x, v.y), fminf(v.z, v.w)));
    }
    smx[t] = mx; smn[t] = mn; __syncthreads();
    for (int s = 128; s > 0; s >>= 1) {
        if (t < s) { smx[t] = fmaxf(smx[t], smx[t + s]); smn[t] = fminf(smn[t], smn[t + s]); }
        __syncthreads();
    }
    if (t == 0) {
        atomicMax(&g_maxbits, __float_as_uint(smx[0]));
        atomicMin(&g_minbits, __float_as_uint(smn[0]));
    }
}

// ================= side stream: pad + tf32-round poi_emb =========================
__global__ void __launch_bounds__(256) k_padpe(const float* __restrict__ pe) {
    int p0 = blockIdx.x * 20;
    for (int it = 0; it < 10; it++) {
        int r = p0 + it * 2 + (threadIdx.x >> 7);
        int d = threadIdx.x & 127;
        float v = 0.f;
        if (r < Pz) v = wmma::__float_to_tf32(pe[r * Fz + d]);
        g_pe[r * Fz + d] = v;
    }
}

// ======== async-stage 64x128 W half-tile into padded smem (512 threads) ==========
__device__ __forceinline__ void cpW(float* __restrict__ Ws, const float* __restrict__ Wg,
                                    int half) {
    const int t = threadIdx.x;
    const float4* src = (const float4*)(Wg + (size_t)(half * 64) * Fz);
    #pragma unroll
    for (int i = t; i < 64 * 32; i += 512) {
        int row = i >> 5, c = i & 31;
        __pipeline_memcpy_async(&Ws[row * WPAD + c * 4], &src[row * 32 + c], 16);
    }
}

#define DOT4(acc, va, vb) acc += (va).x * (vb).x + (va).y * (vb).y + (va).z * (vb).z + (va).w * (vb).w

// ===== single projection (512 thr): dst[25][dstride] = in[25][128] @ Ws^T + b ====
__device__ __forceinline__ void projP(float* __restrict__ dst, int dstride,
                                      const float* __restrict__ in_full,
                                      const float* __restrict__ Ws,
                                      const float* __restrict__ bg, int half) {
    const int t = threadIdx.x;
    const int cp = t & 31, rg = t >> 5;
    const bool r2 = rg < 9;
    float a00 = 0.f, a01 = 0.f, a10 = 0.f, a11 = 0.f;
    const float4* Wa = (const float4*)(Ws + cp * WPAD);
    const float4* Wb = (const float4*)(Ws + (cp + 32) * WPAD);
    const float4* A4 = (const float4*)in_full;
    #pragma unroll 4
    for (int c = 0; c < 32; c++) {
        float4 wa = Wa[c], wb = Wb[c];
        float4 xv = A4[rg * 32 + c];
        DOT4(a00, wa, xv); DOT4(a01, wb, xv);
        if (r2) {
            xv = A4[(rg + 16) * 32 + c];
            DOT4(a10, wa, xv); DOT4(a11, wb, xv);
        }
    }
    float b0 = __ldg(bg + half * 64 + cp);
    float b1 = __ldg(bg + half * 64 + cp + 32);
    dst[rg * dstride + cp     ] = a00 + b0;
    dst[rg * dstride + cp + 32] = a01 + b1;
    if (r2) {
        dst[(rg + 16) * dstride + cp     ] = a10 + b0;
        dst[(rg + 16) * dstride + cp + 32] = a11 + b1;
    }
}

// ===== fused q+k projection =======================================================
__device__ __forceinline__ void projQK(float* __restrict__ qq, float* __restrict__ kq,
                                       const float* __restrict__ inq, const float* __restrict__ inkv,
                                       const float* __restrict__ WsQ, const float* __restrict__ WsK,
                                       const float* __restrict__ bc, int half) {
    const int t = threadIdx.x;
    const int cp = t & 31, rg = t >> 5;
    const bool r2 = rg < 9;
    float q00 = 0.f, q01 = 0.f, q10 = 0.f, q11 = 0.f;
    float k00 = 0.f, k01 = 0.f, k10 = 0.f, k11 = 0.f;
    const float4* WQa = (const float4*)(WsQ + cp * WPAD);
    const float4* WQb = (const float4*)(WsQ + (cp + 32) * WPAD);
    const float4* WKa = (const float4*)(WsK + cp * WPAD);
    const float4* WKb = (const float4*)(WsK + (cp + 32) * WPAD);
    const float4* Aq = (const float4*)inq;
    const float4* Ak = (const float4*)inkv;
    #pragma unroll 4
    for (int c = 0; c < 32; c++) {
        float4 wqa = WQa[c], wqb = WQb[c], wka = WKa[c], wkb = WKb[c];
        float4 xv = Aq[rg * 32 + c];
        DOT4(q00, wqa, xv); DOT4(q01, wqb, xv);
        float4 yv = Ak[rg * 32 + c];
        DOT4(k00, wka, yv); DOT4(k01, wkb, yv);
        if (r2) {
            xv = Aq[(rg + 16) * 32 + c];
            DOT4(q10, wqa, xv); DOT4(q11, wqb, xv);
            yv = Ak[(rg + 16) * 32 + c];
            DOT4(k10, wka, yv); DOT4(k11, wkb, yv);
        }
    }
    float bq0 = __ldg(bc + half * 64 + cp);
    float bq1 = __ldg(bc + half * 64 + cp + 32);
    float bk0 = __ldg(bc + Fz + half * 64 + cp);
    float bk1 = __ldg(bc + Fz + half * 64 + cp + 32);
    qq[rg * 64 + cp     ] = q00 + bq0;
    qq[rg * 64 + cp + 32] = q01 + bq1;
    kq[rg * 64 + cp     ] = k00 + bk0;
    kq[rg * 64 + cp + 32] = k01 + bk1;
    if (r2) {
        qq[(rg + 16) * 64 + cp     ] = q10 + bq0;
        qq[(rg + 16) * 64 + cp + 32] = q11 + bq1;
        kq[(rg + 16) * 64 + cp     ] = k10 + bk0;
        kq[(rg + 16) * 64 + cp + 32] = k11 + bk1;
    }
}

// ================= A kernel: fused qk + v + corr ==================================
__global__ void __launch_bounds__(512, 2) k_A(
        const float* q0, const float* kv0, const float* W0, const float* b0, float* v0, float* m0,
        const float* q1, const float* kv1, const float* W1, const float* b1, float* v1, float* m1) {
    extern __shared__ float sm[];
    float* inq  = sm;               // 3200
    float* inkv = sm + 3200;        // 3200
    float* qq   = sm + 6400;        // 1600
    float* kq   = sm + 8000;        // 1600
    float* WsQ  = sm + 9600;        // 8448
    float* WsK  = sm + 9600 + WHS;  // 8448
    const int bid = blockIdx.x, t = threadIdx.x;
    const int op = bid >> 7, b = (bid >> 1) & 63, half = bid & 1;
    const float* qg  = op ? q1  : q0;
    const float* kvg = op ? kv1 : kv0;
    const float* Wc  = op ? W1  : W0;
    const float* bc  = op ? b1  : b0;
    float* vd = op ? v1 : v0;
    float* md = op ? m1 : m0;

    const float4* qs = (const float4*)(qg + (size_t)b * SLC);
    for (int i = t; i < SLC / 4; i += 512)
        __pipeline_memcpy_async(&((float4*)inq)[i], &qs[i], 16);
    const float* kbuf = inq;
    if (kvg != qg) {
        const float4* ks = (const float4*)(kvg + (size_t)b * SLC);
        for (int i = t; i < SLC / 4; i += 512)
            __pipeline_memcpy_async(&((float4*)inkv)[i], &ks[i], 16);
        kbuf = inkv;
    }
    cpW(WsQ, Wc, half);
    cpW(WsK, Wc + 1 * Fz * Fz, half);
    __pipeline_commit();
    __pipeline_wait_prior(0);
    __syncthreads();

    projQK(qq, kq, inq, kbuf, WsQ, WsK, bc, half);
    __syncthreads();

    cpW(WsQ, Wc + 2 * Fz * Fz, half);     // Wv
    __pipeline_commit();
    __pipeline_wait_prior(0);
    __syncthreads();
    projP(vd + (size_t)b * SLC + half * 64, Fz, kbuf, WsQ, bc + 2 * Fz, half);

    // partial circular correlation over own 64 dims
    const float4* q4 = (const float4*)qq;
    const float4* k4 = (const float4*)kq;
    int w = t >> 5, lane = t & 31;
    for (int tau = w; tau < Lz; tau += 16) {
        float s = 0.f;
        for (int i = lane; i < Lz * 16; i += 32) {
            int n = i >> 4, d4 = i & 15;
            int np = n + tau; if (np >= Lz) np -= Lz;
            float4 a = q4[np * 16 + d4];
            float4 bb = k4[i];
            s += a.x * bb.x + a.y * bb.y + a.z * bb.z + a.w * bb.w;
        }
        #pragma unroll
        for (int off = 16; off > 0; off >>= 1) s += __shfl_down_sync(0xffffffffu, s, off);
        if (lane == 0) md[half * Bz * Lz + b * Lz + tau] = s;
    }
}

// ================= B kernel: topk + agg + out-proj (512 threads) ==================
__global__ void __launch_bounds__(512, 2) k_B(
        const float* m0, const float* v0, const float* W0, const float* b0, float* d0,
        const float* m1, const float* v1, const float* W1, const float* b1, float* d1) {
    extern __shared__ float sm[];
    float* ms  = sm;               // 1600
    float* ag  = sm + 1600;        // 3200
    float* vss = sm + 4800;        // 3200
    float* Ws  = sm + 8000;        // 8448
    __shared__ float s_gms[Lz];
    __shared__ int   s_idx[3];
    __shared__ float s_tc[3];
    const int idx = blockIdx.x, t = threadIdx.x;
    const int op = idx >> 7, b = (idx >> 1) & 63, half = idx & 1;
    const float* mh = op ? m1 : m0;
    const float* vs = op ? v1 : v0;
    const float* Wp = op ? W1 : W0;
    const float* bp = op ? b1 : b0;
    float* dst = op ? d1 : d0;

    {
        const float4* vb4 = (const float4*)(vs + (size_t)b * SLC);
        for (int i = t; i < SLC / 4; i += 512)
            __pipeline_memcpy_async(&((float4*)vss)[i], &vb4[i], 16);
        cpW(Ws, Wp, half);
        __pipeline_commit();
    }

    for (int i = t; i < Bz * Lz; i += 512)
        ms[i] = (mh[i] + mh[Bz * Lz + i]) * (1.0f / Fz);
    __syncthreads();
    if (t < Lz) {
        float s = 0.f;
        for (int bb = 0; bb < Bz; bb++) s += ms[bb * Lz + t];
        s_gms[t] = s;
    }
    __syncthreads();
    if (t == 0) {
        int id0 = 0, id1 = 0, id2 = 0;
        float v0v = -1e38f, v1v = -1e38f, v2v = -1e38f;
        for (int j = 0; j < Lz; j++) {
            float v = s_gms[j];
            if (v > v0v)      { v2v = v1v; id2 = id1; v1v = v0v; id1 = id0; v0v = v; id0 = j; }
            else if (v > v1v) { v2v = v1v; id2 = id1; v1v = v; id1 = j; }
            else if (v > v2v) { v2v = v; id2 = j; }
        }
        float w0 = ms[b * Lz + id0], w1 = ms[b * Lz + id1], w2 = ms[b * Lz + id2];
        float mx = fmaxf(w0, fmaxf(w1, w2));
        float e0 = expf(w0 - mx), e1 = expf(w1 - mx), e2 = expf(w2 - mx);
        float inv = 1.0f / (e0 + e1 + e2);
        s_tc[0] = e0 * inv; s_tc[1] = e1 * inv; s_tc[2] = e2 * inv;
        s_idx[0] = id0; s_idx[1] = id1; s_idx[2] = id2;
    }
    __pipeline_wait_prior(0);
    __syncthreads();
    {
        int i0 = s_idx[0], i1 = s_idx[1], i2 = s_idx[2];
        float c0 = s_tc[0], c1 = s_tc[1], c2 = s_tc[2];
        const float4* vb4 = (const float4*)vss;
        float4* ag4 = (float4*)ag;
        for (int i = t; i < Lz * 32; i += 512) {
            int l = i >> 5, d4 = i & 31;
            int p0 = l + i0; if (p0 >= Lz) p0 -= Lz;
            int p1 = l + i1; if (p1 >= Lz) p1 -= Lz;
            int p2 = l + i2; if (p2 >= Lz) p2 -= Lz;
            float4 x0 = vb4[p0 * 32 + d4];
            float4 x1 = vb4[p1 * 32 + d4];
            float4 x2 = vb4[p2 * 32 + d4];
            float4 r;
            r.x = c0 * x0.x + c1 * x1.x + c2 * x2.x;
            r.y = c0 * x0.y + c1 * x1.y + c2 * x2.y;
            r.z = c0 * x0.z + c1 * x1.z + c2 * x2.z;
            r.w = c0 * x0.w + c1 * x1.w + c2 * x2.w;
            ag4[i] = r;
        }
    }
    __syncthreads();
    projP(dst + (size_t)b * SLC + half * 64, Fz, ag, Ws, bp, half);
}

// ================= final: POI (smem-staged tf32 WMMA + fused epilogue) + CAT ======
// POI part: grid PTILES*32 blocks; N-tile=128 (one ptile), M=64 (2 batches)
__global__ void __launch_bounds__(256) k_final(
        const float* __restrict__ outp, const float* __restrict__ outcp,
        const int* __restrict__ poi,  const float* __restrict__ Dm,
        const float* __restrict__ ce, const float* __restrict__ vw,
        const float* __restrict__ vbp, float* __restrict__ dst_poi,
        float* __restrict__ dst_cat) {
    extern __shared__ float sm[];
    const int bid = blockIdx.x, t = threadIdx.x;

    if (bid < PTILES * 32) {
        float* peS = sm;                 // 128 x PES (17408 floats = 69632 B)
        float* a_s = sm + 128 * PES;     // 64 x 128  (8192 floats = 32768 B)
        float* S   = sm;                 // overlays peS after MMA (64 x PES)
        __shared__ int   rows_s[50];
        __shared__ float vws[Lz];
        const int wid = t >> 5;
        const int ptile = bid % PTILES, b0 = (bid / PTILES) * 2;
        const int p0 = ptile * 128;

        // stage pe tile [p0 .. p0+127][0..127] -> peS (async)
        {
            const float4* src = (const float4*)(g_pe + (size_t)p0 * Fz);
            for (int i = t; i < 128 * 32; i += 256) {
                int row = i >> 5, c = i & 31;
                __pipeline_memcpy_async(&peS[row * PES + c * 4], &src[row * 32 + c], 16);
            }
            __pipeline_commit();
        }
        // load A (out rows, tf32-rounded) while pe streams in
        for (int i = t; i < 64 * 128; i += 256) {
            int r = i >> 7, d = i & 127;
            int l = r & 31, bb = b0 + (r >> 5);
            float v = 0.f;
            if (l < Lz) v = wmma::__float_to_tf32(outp[((bb * Lz) + l) * Fz + d]);
            a_s[i] = v;
        }
        if (t < 50) rows_s[t] = poi[(b0 + t / Lz) * Lz + (t % Lz)];
        if (t < Lz) vws[t] = vw[t];
        __pipeline_wait_prior(0);
        __syncthreads();

        // MMA: 8 warps x (N=16 each), M=64 -> facc[4]
        wmma::fragment<wmma::matrix_a, 16, 16, 8, wmma::precision::tf32, wmma::row_major> fa;
        wmma::fragment<wmma::matrix_b, 16, 16, 8, wmma::precision::tf32, wmma::col_major> fb;
        wmma::fragment<wmma::accumulator, 16, 16, 8, float> facc[4];
        #pragma unroll
        for (int m = 0; m < 4; m++) wmma::fill_fragment(facc[m], 0.f);

        const float* peW = peS + (size_t)(wid * 16) * PES;   // this warp's 16 B-columns
        for (int k = 0; k < 128; k += 8) {
            wmma::load_matrix_sync(fb, peW + k, PES);
            #pragma unroll
            for (int m = 0; m < 4; m++) {
                wmma::load_matrix_sync(fa, a_s + (m * 16) * Fz + k, Fz);
                wmma::mma_sync(facc[m], fa, fb, facc[m]);
            }
        }
        __syncthreads();   // peS no longer needed; S overlays it
        #pragma unroll
        for (int m = 0; m < 4; m++)
            wmma::store_matrix_sync(S + (m * 16) * PES + wid * 16, facc[m], PES, wmma::mem_row_major);
        __syncthreads();

        // epilogue: one (batch, p) per thread
        {
            int bb = t >> 7;            // 0 or 1
            int pl = t & 127;
            int p = p0 + pl;
            if (p < Pz) {
                float neginv = -1.f / (__uint_as_float(g_maxbits) - __uint_as_float(g_minbits));
                float bias = vbp[0];
                float r = 0.f;
                #pragma unroll
                for (int l = 0; l < Lz; l++) {
                    float s = S[(bb * 32 + l) * PES + pl];
                    float d = __ldg(&Dm[(size_t)rows_s[bb * Lz + l] * Pz + p]);
                    r += s * __expf(d * neginv) * vws[l];
                }
                dst_poi[(size_t)(b0 + bb) * Pz + p] = r + bias;
            }
        }
    } else {
        int b = bid - PTILES * 32;
        float* y = sm;
        if (t < Fz) {
            float s = 0.f;
            for (int l = 0; l < Lz; l++) s += __ldg(&vw[l]) * outcp[(size_t)b * SLC + l * Fz + t];
            y[t] = s;
        }
        __syncthreads();
        int w = t >> 5, lane = t & 31;
        float bias = __ldg(vbp);
        const float4* Y4 = (const float4*)y;
        float4 yv = Y4[lane];
        for (int c = w; c < Cz; c += 8) {
            const float4* C4 = (const float4*)(ce + (size_t)c * Fz);
            float4 cv = __ldg(&C4[lane]);
            float s = cv.x * yv.x + cv.y * yv.y + cv.z * yv.z + cv.w * yv.w;
            #pragma unroll
            for (int off = 16; off > 0; off >>= 1) s += __shfl_down_sync(0xffffffffu, s, off);
            if (lane == 0) dst_cat[b * Cz + c] = s + bias;
        }
    }
}

// ---------------- host driver ----------------------------------------------------
extern "C" void kernel_launch(void* const* d_in, const int* in_sizes, int n_in,
                              void* d_out, int out_size) {
    const int*   user = (const int*)d_in[0];
    const int*   poi  = (const int*)d_in[1];
    const int*   cat  = (const int*)d_in[2];
    const int*   tod  = (const int*)d_in[5];
    const int*   dow  = (const int*)d_in[6];
    const float* ue   = (const float*)d_in[8];
    const float* pe   = (const float*)d_in[9];
    const float* ce   = (const float*)d_in[10];
    const float* te   = (const float*)d_in[11];
    const float* de   = (const float*)d_in[12];
    const float* uec  = (const float*)d_in[13];
    const float* tec  = (const float*)d_in[14];
    const float* dec  = (const float*)d_in[15];
    const float* W    = (const float*)d_in[16];
    const float* Bvv  = (const float*)d_in[17];
    const float* vw   = (const float*)d_in[18];
    const float* vb   = (const float*)d_in[19];
    const float* Dm   = (const float*)d_in[20];
    float* out = (float*)d_out;

    const int ASM = (3200 + 3200 + 1600 + 1600 + 2 * WHS) * 4;  // 105984 B
    const int BSM = (1600 + 3200 + 3200 + WHS) * 4;             // 65792 B
    const int FSM = (128 * PES + 64 * Fz) * 4;                  // 102400 B

    static cudaStream_t s2 = nullptr;
    static cudaEvent_t evFork = nullptr, evJoin = nullptr;
    static int init_done = 0;
    if (!init_done) {
        cudaFuncSetAttribute(k_A,     cudaFuncAttributeMaxDynamicSharedMemorySize, ASM);
        cudaFuncSetAttribute(k_B,     cudaFuncAttributeMaxDynamicSharedMemorySize, BSM);
        cudaFuncSetAttribute(k_final, cudaFuncAttributeMaxDynamicSharedMemorySize, FSM);
        cudaStreamCreateWithFlags(&s2, cudaStreamNonBlocking);
        cudaEventCreateWithFlags(&evFork, cudaEventDisableTiming);
        cudaEventCreateWithFlags(&evJoin, cudaEventDisableTiming);
        init_done = 1;
    }

    float* stp;  cudaGetSymbolAddress((void**)&stp, g_st);
    float* vp;   cudaGetSymbolAddress((void**)&vp,  g_v8);
    float* mp;   cudaGetSymbolAddress((void**)&mp,  g_meanH);
    #define ST(i)  (stp + (size_t)(i) * BL * Fz)
    #define VV(i)  (vp  + (size_t)(i) * BL * Fz)
    #define MM(i)  (mp  + (size_t)(i) * 2 * Bz * Lz)
    #define WQKV(c) (W   + (size_t)(c) * 4 * Fz * Fz)
    #define WPRJ(c) (W   + (size_t)(c) * 4 * Fz * Fz + 3 * Fz * Fz)
    #define BQKV(c) (Bvv + (size_t)(c) * 4 * Fz)
    #define BPRJ(c) (Bvv + (size_t)(c) * 4 * Fz + 3 * Fz)

    // fork side stream: minmax + padpe run concurrently with the layer chain
    cudaEventRecord(evFork, 0);
    cudaStreamWaitEvent(s2, evFork, 0);
    k_minmax<<<3200, 256, 0, s2>>>(poi, Dm);
    k_padpe<<<512, 256, 0, s2>>>(pe);
    cudaEventRecord(evJoin, s2);

    k_embed<<<800, 256>>>(user, poi, cat, tod, dow, ue, pe, ce, te, de, uec, tec, dec);

    // c0: AC(x,x) ; c1: AC(xc,xc)
    k_A<<<256, 512, ASM>>>(ST(0), ST(0), WQKV(0), BQKV(0), VV(0), MM(0),
                           ST(1), ST(1), WQKV(1), BQKV(1), VV(1), MM(1));
    k_B<<<256, 512, BSM>>>(MM(0), VV(0), WPRJ(0), BPRJ(0), ST(2),
                           MM(1), VV(1), WPRJ(1), BPRJ(1), ST(3));
    // c2: AC(out1, outc1)
    k_A<<<128, 512, ASM>>>(ST(2), ST(3), WQKV(2), BQKV(2), VV(2), MM(2),
                           nullptr, nullptr, nullptr, nullptr, nullptr, nullptr);
    k_B<<<128, 512, BSM>>>(MM(2), VV(2), WPRJ(2), BPRJ(2), ST(4),
                           nullptr, nullptr, nullptr, nullptr, nullptr);
    // c3: AC(outc1, out2) ; c4: AC(out2, out2)
    k_A<<<256, 512, ASM>>>(ST(3), ST(4), WQKV(3), BQKV(3), VV(3), MM(3),
                           ST(4), ST(4), WQKV(4), BQKV(4), VV(4), MM(4));
    k_B<<<256, 512, BSM>>>(MM(3), VV(3), WPRJ(3), BPRJ(3), ST(5),
                           MM(4), VV(4), WPRJ(4), BPRJ(4), ST(6));
    // c5: AC(outc2, outc2)
    k_A<<<128, 512, ASM>>>(ST(5), ST(5), WQKV(5), BQKV(5), VV(5), MM(5),
                           nullptr, nullptr, nullptr, nullptr, nullptr, nullptr);
    k_B<<<128, 512, BSM>>>(MM(5), VV(5), WPRJ(5), BPRJ(5), ST(7),
                           nullptr, nullptr, nullptr, nullptr, nullptr);
    // c6: AC(out3, outc3)
    k_A<<<128, 512, ASM>>>(ST(6), ST(7), WQKV(6), BQKV(6), VV(6), MM(6),
                           nullptr, nullptr, nullptr, nullptr, nullptr, nullptr);
    k_B<<<128, 512, BSM>>>(MM(6), VV(6), WPRJ(6), BPRJ(6), ST(8),
                           nullptr, nullptr, nullptr, nullptr, nullptr);
    // c7: AC(outc3, out4)
    k_A<<<128, 512, ASM>>>(ST(7), ST(8), WQKV(7), BQKV(7), VV(7), MM(7),
                           nullptr, nullptr, nullptr, nullptr, nullptr, nullptr);
    k_B<<<128, 512, BSM>>>(MM(7), VV(7), WPRJ(7), BPRJ(7), ST(9),
                           nullptr, nullptr, nullptr, nullptr, nullptr);

    // join side stream, then final: POI (79*32 blocks) + CAT (64 blocks)
    cudaStreamWaitEvent(0, evJoin, 0);
    k_final<<<PTILES * 32 + 64, 256, FSM>>>(ST(8), ST(9), poi, Dm, ce, vw, vb,
                                            out, out + (size_t)Bz * Pz);
}

// round 17
// speedup vs baseline: 1.3219x; 1.3219x over previous
#include <cuda_runtime.h>
#include <cuda_pipeline.h>
#include <math.h>
#include <mma.h>
using namespace nvcuda;

#define Bz   64
#define Lz   25
#define Fz   128
#define Pz   10000
#define Cz   400
#define BL   1600
#define SLC  (Lz * Fz)          // 3200
#define WPAD 132
#define WHS  (64 * WPAD)        // 8448 floats
#define PTILES 79               // ceil(10000/128)
#define PES  136                // padded pe row stride (floats, mult of 8)
#define APES 136                // padded A row stride (floats, mult of 8)

// ---------------- device scratch -------------------------------------------------
__device__ __align__(16) float g_st[10][BL * Fz];
__device__ __align__(16) float g_v8[8][BL * Fz];
__device__ __align__(16) float g_meanH[8][2 * Bz * Lz];
__device__ __align__(16) float g_pe[10240 * Fz];
__device__ unsigned g_maxbits = 0u;
__device__ unsigned g_minbits = 0x7F7FFFFFu;

// ================= embed ==========================================================
__global__ void __launch_bounds__(256) k_embed(
        const int* __restrict__ user, const int* __restrict__ poi,
        const int* __restrict__ cat,  const int* __restrict__ tod,
        const int* __restrict__ dow,
        const float* __restrict__ ue,  const float* __restrict__ pe,
        const float* __restrict__ ce,  const float* __restrict__ te,
        const float* __restrict__ de,  const float* __restrict__ uec,
        const float* __restrict__ tec, const float* __restrict__ dec) {
    int r = 2 * blockIdx.x + (threadIdx.x >> 7);
    int d = threadIdx.x & 127;
    int u = user[r], p = poi[r], c = cat[r], td = tod[r], dw = dow[r];
    g_st[0][r * Fz + d] = ue[u * Fz + d]  + pe[p * Fz + d] + te[td * Fz + d]  + de[dw * Fz + d];
    g_st[1][r * Fz + d] = uec[u * Fz + d] + ce[c * Fz + d] + tec[td * Fz + d] + dec[dw * Fz + d];
}

// ================= side stream: minmax over gathered D rows ======================
__global__ void __launch_bounds__(256) k_minmax(const int* __restrict__ poi,
                                                const float* __restrict__ Dm) {
    __shared__ float smx[256], smn[256];
    const int t = threadIdx.x;
    int rid = blockIdx.x;
    int row = poi[rid >> 1];
    int part = rid & 1;
    const float4* rp4 = (const float4*)(Dm + (size_t)row * Pz);
    float mx = -1e30f, mn = 1e30f;
    for (int p = part * 1250 + t; p < (part + 1) * 1250; p += 256) {
        float4 v = __ldg(rp4 + p);
        mx = fmaxf(mx, fmaxf(fmaxf(v.x, v.y), fmaxf(v.z, v.w)));
        mn = fminf(mn, fminf(fminf(v.x, v.y), fminf(v.z, v.w)));
    }
    smx[t] = mx; smn[t] = mn; __syncthreads();
    for (int s = 128; s > 0; s >>= 1) {
        if (t < s) { smx[t] = fmaxf(smx[t], smx[t + s]); smn[t] = fminf(smn[t], smn[t + s]); }
        __syncthreads();
    }
    if (t == 0) {
        atomicMax(&g_maxbits, __float_as_uint(smx[0]));
        atomicMin(&g_minbits, __float_as_uint(smn[0]));
    }
}

// ================= side stream: pad + tf32-round poi_emb =========================
__global__ void __launch_bounds__(256) k_padpe(const float* __restrict__ pe) {
    int p0 = blockIdx.x * 20;
    for (int it = 0; it < 10; it++) {
        int r = p0 + it * 2 + (threadIdx.x >> 7);
        int d = threadIdx.x & 127;
        float v = 0.f;
        if (r < Pz) v = wmma::__float_to_tf32(pe[r * Fz + d]);
        g_pe[r * Fz + d] = v;
    }
}

// ======== async-stage 64x128 W half-tile into padded smem (512 threads) ==========
__device__ __forceinline__ void cpW(float* __restrict__ Ws, const float* __restrict__ Wg,
                                    int half) {
    const int t = threadIdx.x;
    const float4* src = (const float4*)(Wg + (size_t)(half * 64) * Fz);
    #pragma unroll
    for (int i = t; i < 64 * 32; i += 512) {
        int row = i >> 5, c = i & 31;
        __pipeline_memcpy_async(&Ws[row * WPAD + c * 4], &src[row * 32 + c], 16);
    }
}

#define DOT4(acc, va, vb) acc += (va).x * (vb).x + (va).y * (vb).y + (va).z * (vb).z + (va).w * (vb).w

// ===== single projection (512 thr): dst[25][dstride] = in[25][128] @ Ws^T + b ====
__device__ __forceinline__ void projP(float* __restrict__ dst, int dstride,
                                      const float* __restrict__ in_full,
                                      const float* __restrict__ Ws,
                                      const float* __restrict__ bg, int half) {
    const int t = threadIdx.x;
    const int cp = t & 31, rg = t >> 5;
    const bool r2 = rg < 9;
    float a00 = 0.f, a01 = 0.f, a10 = 0.f, a11 = 0.f;
    const float4* Wa = (const float4*)(Ws + cp * WPAD);
    const float4* Wb = (const float4*)(Ws + (cp + 32) * WPAD);
    const float4* A4 = (const float4*)in_full;
    #pragma unroll 4
    for (int c = 0; c < 32; c++) {
        float4 wa = Wa[c], wb = Wb[c];
        float4 xv = A4[rg * 32 + c];
        DOT4(a00, wa, xv); DOT4(a01, wb, xv);
        if (r2) {
            xv = A4[(rg + 16) * 32 + c];
            DOT4(a10, wa, xv); DOT4(a11, wb, xv);
        }
    }
    float b0 = __ldg(bg + half * 64 + cp);
    float b1 = __ldg(bg + half * 64 + cp + 32);
    dst[rg * dstride + cp     ] = a00 + b0;
    dst[rg * dstride + cp + 32] = a01 + b1;
    if (r2) {
        dst[(rg + 16) * dstride + cp     ] = a10 + b0;
        dst[(rg + 16) * dstride + cp + 32] = a11 + b1;
    }
}

// ===== fused q+k projection =======================================================
__device__ __forceinline__ void projQK(float* __restrict__ qq, float* __restrict__ kq,
                                       const float* __restrict__ inq, const float* __restrict__ inkv,
                                       const float* __restrict__ WsQ, const float* __restrict__ WsK,
                                       const float* __restrict__ bc, int half) {
    const int t = threadIdx.x;
    const int cp = t & 31, rg = t >> 5;
    const bool r2 = rg < 9;
    float q00 = 0.f, q01 = 0.f, q10 = 0.f, q11 = 0.f;
    float k00 = 0.f, k01 = 0.f, k10 = 0.f, k11 = 0.f;
    const float4* WQa = (const float4*)(WsQ + cp * WPAD);
    const float4* WQb = (const float4*)(WsQ + (cp + 32) * WPAD);
    const float4* WKa = (const float4*)(WsK + cp * WPAD);
    const float4* WKb = (const float4*)(WsK + (cp + 32) * WPAD);
    const float4* Aq = (const float4*)inq;
    const float4* Ak = (const float4*)inkv;
    #pragma unroll 4
    for (int c = 0; c < 32; c++) {
        float4 wqa = WQa[c], wqb = WQb[c], wka = WKa[c], wkb = WKb[c];
        float4 xv = Aq[rg * 32 + c];
        DOT4(q00, wqa, xv); DOT4(q01, wqb, xv);
        float4 yv = Ak[rg * 32 + c];
        DOT4(k00, wka, yv); DOT4(k01, wkb, yv);
        if (r2) {
            xv = Aq[(rg + 16) * 32 + c];
            DOT4(q10, wqa, xv); DOT4(q11, wqb, xv);
            yv = Ak[(rg + 16) * 32 + c];
            DOT4(k10, wka, yv); DOT4(k11, wkb, yv);
        }
    }
    float bq0 = __ldg(bc + half * 64 + cp);
    float bq1 = __ldg(bc + half * 64 + cp + 32);
    float bk0 = __ldg(bc + Fz + half * 64 + cp);
    float bk1 = __ldg(bc + Fz + half * 64 + cp + 32);
    qq[rg * 64 + cp     ] = q00 + bq0;
    qq[rg * 64 + cp + 32] = q01 + bq1;
    kq[rg * 64 + cp     ] = k00 + bk0;
    kq[rg * 64 + cp + 32] = k01 + bk1;
    if (r2) {
        qq[(rg + 16) * 64 + cp     ] = q10 + bq0;
        qq[(rg + 16) * 64 + cp + 32] = q11 + bq1;
        kq[(rg + 16) * 64 + cp     ] = k10 + bk0;
        kq[(rg + 16) * 64 + cp + 32] = k11 + bk1;
    }
}

// ================= A kernel: fused qk + v + corr ==================================
__global__ void __launch_bounds__(512, 2) k_A(
        const float* q0, const float* kv0, const float* W0, const float* b0, float* v0, float* m0,
        const float* q1, const float* kv1, const float* W1, const float* b1, float* v1, float* m1) {
    extern __shared__ float sm[];
    float* inq  = sm;               // 3200
    float* inkv = sm + 3200;        // 3200
    float* qq   = sm + 6400;        // 1600
    float* kq   = sm + 8000;        // 1600
    float* WsQ  = sm + 9600;        // 8448
    float* WsK  = sm + 9600 + WHS;  // 8448
    const int bid = blockIdx.x, t = threadIdx.x;
    const int op = bid >> 7, b = (bid >> 1) & 63, half = bid & 1;
    const float* qg  = op ? q1  : q0;
    const float* kvg = op ? kv1 : kv0;
    const float* Wc  = op ? W1  : W0;
    const float* bc  = op ? b1  : b0;
    float* vd = op ? v1 : v0;
    float* md = op ? m1 : m0;

    const float4* qs = (const float4*)(qg + (size_t)b * SLC);
    for (int i = t; i < SLC / 4; i += 512)
        __pipeline_memcpy_async(&((float4*)inq)[i], &qs[i], 16);
    const float* kbuf = inq;
    if (kvg != qg) {
        const float4* ks = (const float4*)(kvg + (size_t)b * SLC);
        for (int i = t; i < SLC / 4; i += 512)
            __pipeline_memcpy_async(&((float4*)inkv)[i], &ks[i], 16);
        kbuf = inkv;
    }
    cpW(WsQ, Wc, half);
    cpW(WsK, Wc + 1 * Fz * Fz, half);
    __pipeline_commit();
    __pipeline_wait_prior(0);
    __syncthreads();

    projQK(qq, kq, inq, kbuf, WsQ, WsK, bc, half);
    __syncthreads();

    cpW(WsQ, Wc + 2 * Fz * Fz, half);     // Wv
    __pipeline_commit();
    __pipeline_wait_prior(0);
    __syncthreads();
    projP(vd + (size_t)b * SLC + half * 64, Fz, kbuf, WsQ, bc + 2 * Fz, half);

    // partial circular correlation over own 64 dims
    const float4* q4 = (const float4*)qq;
    const float4* k4 = (const float4*)kq;
    int w = t >> 5, lane = t & 31;
    for (int tau = w; tau < Lz; tau += 16) {
        float s = 0.f;
        for (int i = lane; i < Lz * 16; i += 32) {
            int n = i >> 4, d4 = i & 15;
            int np = n + tau; if (np >= Lz) np -= Lz;
            float4 a = q4[np * 16 + d4];
            float4 bb = k4[i];
            s += a.x * bb.x + a.y * bb.y + a.z * bb.z + a.w * bb.w;
        }
        #pragma unroll
        for (int off = 16; off > 0; off >>= 1) s += __shfl_down_sync(0xffffffffu, s, off);
        if (lane == 0) md[half * Bz * Lz + b * Lz + tau] = s;
    }
}

// ================= B kernel: topk + agg + out-proj (512 threads) ==================
__global__ void __launch_bounds__(512, 2) k_B(
        const float* m0, const float* v0, const float* W0, const float* b0, float* d0,
        const float* m1, const float* v1, const float* W1, const float* b1, float* d1) {
    extern __shared__ float sm[];
    float* ms  = sm;               // 1600
    float* ag  = sm + 1600;        // 3200
    float* vss = sm + 4800;        // 3200
    float* Ws  = sm + 8000;        // 8448
    __shared__ float s_gms[Lz];
    __shared__ int   s_idx[3];
    __shared__ float s_tc[3];
    const int idx = blockIdx.x, t = threadIdx.x;
    const int op = idx >> 7, b = (idx >> 1) & 63, half = idx & 1;
    const float* mh = op ? m1 : m0;
    const float* vs = op ? v1 : v0;
    const float* Wp = op ? W1 : W0;
    const float* bp = op ? b1 : b0;
    float* dst = op ? d1 : d0;

    {
        const float4* vb4 = (const float4*)(vs + (size_t)b * SLC);
        for (int i = t; i < SLC / 4; i += 512)
            __pipeline_memcpy_async(&((float4*)vss)[i], &vb4[i], 16);
        cpW(Ws, Wp, half);
        __pipeline_commit();
    }

    for (int i = t; i < Bz * Lz; i += 512)
        ms[i] = (mh[i] + mh[Bz * Lz + i]) * (1.0f / Fz);
    __syncthreads();
    if (t < Lz) {
        float s = 0.f;
        for (int bb = 0; bb < Bz; bb++) s += ms[bb * Lz + t];
        s_gms[t] = s;
    }
    __syncthreads();
    if (t == 0) {
        int id0 = 0, id1 = 0, id2 = 0;
        float v0v = -1e38f, v1v = -1e38f, v2v = -1e38f;
        for (int j = 0; j < Lz; j++) {
            float v = s_gms[j];
            if (v > v0v)      { v2v = v1v; id2 = id1; v1v = v0v; id1 = id0; v0v = v; id0 = j; }
            else if (v > v1v) { v2v = v1v; id2 = id1; v1v = v; id1 = j; }
            else if (v > v2v) { v2v = v; id2 = j; }
        }
        float w0 = ms[b * Lz + id0], w1 = ms[b * Lz + id1], w2 = ms[b * Lz + id2];
        float mx = fmaxf(w0, fmaxf(w1, w2));
        float e0 = expf(w0 - mx), e1 = expf(w1 - mx), e2 = expf(w2 - mx);
        float inv = 1.0f / (e0 + e1 + e2);
        s_tc[0] = e0 * inv; s_tc[1] = e1 * inv; s_tc[2] = e2 * inv;
        s_idx[0] = id0; s_idx[1] = id1; s_idx[2] = id2;
    }
    __pipeline_wait_prior(0);
    __syncthreads();
    {
        int i0 = s_idx[0], i1 = s_idx[1], i2 = s_idx[2];
        float c0 = s_tc[0], c1 = s_tc[1], c2 = s_tc[2];
        const float4* vb4 = (const float4*)vss;
        float4* ag4 = (float4*)ag;
        for (int i = t; i < Lz * 32; i += 512) {
            int l = i >> 5, d4 = i & 31;
            int p0 = l + i0; if (p0 >= Lz) p0 -= Lz;
            int p1 = l + i1; if (p1 >= Lz) p1 -= Lz;
            int p2 = l + i2; if (p2 >= Lz) p2 -= Lz;
            float4 x0 = vb4[p0 * 32 + d4];
            float4 x1 = vb4[p1 * 32 + d4];
            float4 x2 = vb4[p2 * 32 + d4];
            float4 r;
            r.x = c0 * x0.x + c1 * x1.x + c2 * x2.x;
            r.y = c0 * x0.y + c1 * x1.y + c2 * x2.y;
            r.z = c0 * x0.z + c1 * x1.z + c2 * x2.z;
            r.w = c0 * x0.w + c1 * x1.w + c2 * x2.w;
            ag4[i] = r;
        }
    }
    __syncthreads();
    projP(dst + (size_t)b * SLC + half * 64, Fz, ag, Ws, bp, half);
}

// ================= final: POI (padded smem tf32 WMMA + fused epilogue) + CAT ======
__global__ void __launch_bounds__(256) k_final(
        const float* __restrict__ outp, const float* __restrict__ outcp,
        const int* __restrict__ poi,  const float* __restrict__ Dm,
        const float* __restrict__ ce, const float* __restrict__ vw,
        const float* __restrict__ vbp, float* __restrict__ dst_poi,
        float* __restrict__ dst_cat) {
    extern __shared__ float sm[];
    const int bid = blockIdx.x, t = threadIdx.x;

    if (bid < PTILES * 32) {
        float* peS = sm;                   // 128 x PES  (17408 floats)
        float* a_s = sm + 128 * PES;       // 64 x APES  (8704 floats)
        float* S   = sm;                   // overlays peS after MMA (64 x PES)
        __shared__ int   rows_s[50];
        __shared__ float vws[Lz];
        const int wid = t >> 5;
        const int ptile = bid % PTILES, b0 = (bid / PTILES) * 2;
        const int p0 = ptile * 128;

        // stage pe tile (async, padded)
        {
            const float4* src = (const float4*)(g_pe + (size_t)p0 * Fz);
            for (int i = t; i < 128 * 32; i += 256) {
                int row = i >> 5, c = i & 31;
                __pipeline_memcpy_async(&peS[row * PES + c * 4], &src[row * 32 + c], 16);
            }
            __pipeline_commit();
        }
        // load A into padded smem (tf32-rounded)
        for (int i = t; i < 64 * 128; i += 256) {
            int r = i >> 7, d = i & 127;
            int l = r & 31, bb = b0 + (r >> 5);
            float v = 0.f;
            if (l < Lz) v = wmma::__float_to_tf32(outp[((bb * Lz) + l) * Fz + d]);
            a_s[r * APES + d] = v;
        }
        if (t < 50) rows_s[t] = poi[(b0 + t / Lz) * Lz + (t % Lz)];
        if (t < Lz) vws[t] = vw[t];
        __pipeline_wait_prior(0);
        __syncthreads();

        // MMA: 8 warps x (N=16 each), M=64
        wmma::fragment<wmma::matrix_a, 16, 16, 8, wmma::precision::tf32, wmma::row_major> fa;
        wmma::fragment<wmma::matrix_b, 16, 16, 8, wmma::precision::tf32, wmma::col_major> fb;
        wmma::fragment<wmma::accumulator, 16, 16, 8, float> facc[4];
        #pragma unroll
        for (int m = 0; m < 4; m++) wmma::fill_fragment(facc[m], 0.f);

        const float* peW = peS + (size_t)(wid * 16) * PES;
        for (int k = 0; k < 128; k += 8) {
            wmma::load_matrix_sync(fb, peW + k, PES);
            #pragma unroll
            for (int m = 0; m < 4; m++) {
                wmma::load_matrix_sync(fa, a_s + (m * 16) * APES + k, APES);
                wmma::mma_sync(facc[m], fa, fb, facc[m]);
            }
        }
        __syncthreads();   // peS no longer needed; S overlays it
        #pragma unroll
        for (int m = 0; m < 4; m++)
            wmma::store_matrix_sync(S + (m * 16) * PES + wid * 16, facc[m], PES, wmma::mem_row_major);
        __syncthreads();

        // epilogue: one (batch, p) per thread
        {
            int bb = t >> 7;
            int pl = t & 127;
            int p = p0 + pl;
            if (p < Pz) {
                float neginv = -1.f / (__uint_as_float(g_maxbits) - __uint_as_float(g_minbits));
                float bias = vbp[0];
                float r = 0.f;
                #pragma unroll
                for (int l = 0; l < Lz; l++) {
                    float s = S[(bb * 32 + l) * PES + pl];
                    float d = __ldg(&Dm[(size_t)rows_s[bb * Lz + l] * Pz + p]);
                    r += s * __expf(d * neginv) * vws[l];
                }
                dst_poi[(size_t)(b0 + bb) * Pz + p] = r + bias;
            }
        }
    } else {
        int b = bid - PTILES * 32;
        float* y = sm;
        if (t < Fz) {
            float s = 0.f;
            for (int l = 0; l < Lz; l++) s += __ldg(&vw[l]) * outcp[(size_t)b * SLC + l * Fz + t];
            y[t] = s;
        }
        __syncthreads();
        int w = t >> 5, lane = t & 31;
        float bias = __ldg(vbp);
        const float4* Y4 = (const float4*)y;
        float4 yv = Y4[lane];
        for (int c = w; c < Cz; c += 8) {
            const float4* C4 = (const float4*)(ce + (size_t)c * Fz);
            float4 cv = __ldg(&C4[lane]);
            float s = cv.x * yv.x + cv.y * yv.y + cv.z * yv.z + cv.w * yv.w;
            #pragma unroll
            for (int off = 16; off > 0; off >>= 1) s += __shfl_down_sync(0xffffffffu, s, off);
            if (lane == 0) dst_cat[b * Cz + c] = s + bias;
        }
    }
}

// ---------------- host driver ----------------------------------------------------
extern "C" void kernel_launch(void* const* d_in, const int* in_sizes, int n_in,
                              void* d_out, int out_size) {
    const int*   user = (const int*)d_in[0];
    const int*   poi  = (const int*)d_in[1];
    const int*   cat  = (const int*)d_in[2];
    const int*   tod  = (const int*)d_in[5];
    const int*   dow  = (const int*)d_in[6];
    const float* ue   = (const float*)d_in[8];
    const float* pe   = (const float*)d_in[9];
    const float* ce   = (const float*)d_in[10];
    const float* te   = (const float*)d_in[11];
    const float* de   = (const float*)d_in[12];
    const float* uec  = (const float*)d_in[13];
    const float* tec  = (const float*)d_in[14];
    const float* dec  = (const float*)d_in[15];
    const float* W    = (const float*)d_in[16];
    const float* Bvv  = (const float*)d_in[17];
    const float* vw   = (const float*)d_in[18];
    const float* vb   = (const float*)d_in[19];
    const float* Dm   = (const float*)d_in[20];
    float* out = (float*)d_out;

    const int ASM = (3200 + 3200 + 1600 + 1600 + 2 * WHS) * 4;  // 105984 B
    const int BSM = (1600 + 3200 + 3200 + WHS) * 4;             // 65792 B
    const int FSM = (128 * PES + 64 * APES) * 4;                // 104448 B

    static cudaStream_t s2 = nullptr;
    static cudaEvent_t evFork = nullptr, evJoin = nullptr;
    static int init_done = 0;
    if (!init_done) {
        cudaFuncSetAttribute(k_A,     cudaFuncAttributeMaxDynamicSharedMemorySize, ASM);
        cudaFuncSetAttribute(k_B,     cudaFuncAttributeMaxDynamicSharedMemorySize, BSM);
        cudaFuncSetAttribute(k_final, cudaFuncAttributeMaxDynamicSharedMemorySize, FSM);
        cudaStreamCreateWithFlags(&s2, cudaStreamNonBlocking);
        cudaEventCreateWithFlags(&evFork, cudaEventDisableTiming);
        cudaEventCreateWithFlags(&evJoin, cudaEventDisableTiming);
        init_done = 1;
    }

    float* stp;  cudaGetSymbolAddress((void**)&stp, g_st);
    float* vp;   cudaGetSymbolAddress((void**)&vp,  g_v8);
    float* mp;   cudaGetSymbolAddress((void**)&mp,  g_meanH);
    #define ST(i)  (stp + (size_t)(i) * BL * Fz)
    #define VV(i)  (vp  + (size_t)(i) * BL * Fz)
    #define MM(i)  (mp  + (size_t)(i) * 2 * Bz * Lz)
    #define WQKV(c) (W   + (size_t)(c) * 4 * Fz * Fz)
    #define WPRJ(c) (W   + (size_t)(c) * 4 * Fz * Fz + 3 * Fz * Fz)
    #define BQKV(c) (Bvv + (size_t)(c) * 4 * Fz)
    #define BPRJ(c) (Bvv + (size_t)(c) * 4 * Fz + 3 * Fz)

    // fork side stream: minmax + padpe run concurrently with the layer chain
    cudaEventRecord(evFork, 0);
    cudaStreamWaitEvent(s2, evFork, 0);
    k_minmax<<<3200, 256, 0, s2>>>(poi, Dm);
    k_padpe<<<512, 256, 0, s2>>>(pe);
    cudaEventRecord(evJoin, s2);

    k_embed<<<800, 256>>>(user, poi, cat, tod, dow, ue, pe, ce, te, de, uec, tec, dec);

    // c0: AC(x,x) ; c1: AC(xc,xc)
    k_A<<<256, 512, ASM>>>(ST(0), ST(0), WQKV(0), BQKV(0), VV(0), MM(0),
                           ST(1), ST(1), WQKV(1), BQKV(1), VV(1), MM(1));
    k_B<<<256, 512, BSM>>>(MM(0), VV(0), WPRJ(0), BPRJ(0), ST(2),
                           MM(1), VV(1), WPRJ(1), BPRJ(1), ST(3));
    // c2: AC(out1, outc1)
    k_A<<<128, 512, ASM>>>(ST(2), ST(3), WQKV(2), BQKV(2), VV(2), MM(2),
                           nullptr, nullptr, nullptr, nullptr, nullptr, nullptr);
    k_B<<<128, 512, BSM>>>(MM(2), VV(2), WPRJ(2), BPRJ(2), ST(4),
                           nullptr, nullptr, nullptr, nullptr, nullptr);
    // c3: AC(outc1, out2) ; c4: AC(out2, out2)
    k_A<<<256, 512, ASM>>>(ST(3), ST(4), WQKV(3), BQKV(3), VV(3), MM(3),
                           ST(4), ST(4), WQKV(4), BQKV(4), VV(4), MM(4));
    k_B<<<256, 512, BSM>>>(MM(3), VV(3), WPRJ(3), BPRJ(3), ST(5),
                           MM(4), VV(4), WPRJ(4), BPRJ(4), ST(6));
    // c5: AC(outc2, outc2)
    k_A<<<128, 512, ASM>>>(ST(5), ST(5), WQKV(5), BQKV(5), VV(5), MM(5),
                           nullptr, nullptr, nullptr, nullptr, nullptr, nullptr);
    k_B<<<128, 512, BSM>>>(MM(5), VV(5), WPRJ(5), BPRJ(5), ST(7),
                           nullptr, nullptr, nullptr, nullptr, nullptr);
    // c6: AC(out3, outc3)
    k_A<<<128, 512, ASM>>>(ST(6), ST(7), WQKV(6), BQKV(6), VV(6), MM(6),
                           nullptr, nullptr, nullptr, nullptr, nullptr, nullptr);
    k_B<<<128, 512, BSM>>>(MM(6), VV(6), WPRJ(6), BPRJ(6), ST(8),
                           nullptr, nullptr, nullptr, nullptr, nullptr);
    // c7: AC(outc3, out4)
    k_A<<<128, 512, ASM>>>(ST(7), ST(8), WQKV(7), BQKV(7), VV(7), MM(7),
                           nullptr, nullptr, nullptr, nullptr, nullptr, nullptr);
    k_B<<<128, 512, BSM>>>(MM(7), VV(7), WPRJ(7), BPRJ(7), ST(9),
                           nullptr, nullptr, nullptr, nullptr, nullptr);

    // join side stream, then final: POI (79*32 blocks) + CAT (64 blocks)
    cudaStreamWaitEvent(0, evJoin, 0);
    k_final<<<PTILES * 32 + 64, 256, FSM>>>(ST(8), ST(9), poi, Dm, ce, vw, vb,
                                            out, out + (size_t)Bz * Pz);
}